// round 11
// baseline (speedup 1.0000x reference)
#include <cuda_runtime.h>
#include <cuda_fp16.h>
#include <math.h>
#include <stdint.h>

// ---------------- problem dims (fixed) ----------------
#define BSZ   8
#define LSEQ  4096
#define HDIM  1024
#define PDIM  512
#define MTOT  (BSZ * LSEQ)        // 32768
#define CHUNKL 128
#define NCHK  (LSEQ / CHUNKL)     // 32
#define NCHUNKS_TOT (BSZ * NCHK)  // 256

#define S1_SCALE 1024.0f
#define S1_INV   (1.0f / 1024.0f)

// ---------------- device scratch ----------------
__device__ float2 g_lbc   [PDIM];
__device__ float2 g_lb128c[PDIM];
__device__ float  g_fac   [2 * PDIM];
__device__ __half g_uh  [(size_t)MTOT * 1024];
__device__ __half g_w1h [(size_t)1024 * 1024];  // rows interleaved: 2p=Re, 2p+1=Im (scaled)
__device__ __half g_w2h [(size_t)1024 * 1024];  // cols interleaved: 2p=C_re, 2p+1=-C_im
__device__ __half g_xsh [(size_t)MTOT * 1024];
__device__ float2 g_cs2 [NCHUNKS_TOT * PDIM];
__device__ float2 g_ci2 [NCHUNKS_TOT * PDIM];

// ---------------- PTX helpers ----------------
__device__ __forceinline__ uint32_t smem_u32(const void* p) {
    uint32_t a;
    asm("{ .reg .u64 t; cvta.to.shared.u64 t, %1; cvt.u32.u64 %0, t; }" : "=r"(a) : "l"(p));
    return a;
}
#define CP_ASYNC16(dst, src) \
    asm volatile("cp.async.cg.shared.global [%0], [%1], 16;" :: "r"(dst), "l"(src) : "memory")
#define CP_COMMIT() asm volatile("cp.async.commit_group;" ::: "memory")
#define CP_WAIT1()  asm volatile("cp.async.wait_group 1;" ::: "memory")

__device__ __forceinline__ void ldsm4(uint32_t* r, uint32_t addr) {
    asm volatile("ldmatrix.sync.aligned.m8n8.x4.shared.b16 {%0,%1,%2,%3}, [%4];"
                 : "=r"(r[0]), "=r"(r[1]), "=r"(r[2]), "=r"(r[3]) : "r"(addr));
}
__device__ __forceinline__ void mma16816(float* d, const uint32_t* a, uint32_t b0, uint32_t b1) {
    asm volatile("mma.sync.aligned.m16n8k16.row.col.f32.f16.f16.f32 "
                 "{%0,%1,%2,%3}, {%4,%5,%6,%7}, {%8,%9}, {%0,%1,%2,%3};"
                 : "+f"(d[0]), "+f"(d[1]), "+f"(d[2]), "+f"(d[3])
                 : "r"(a[0]), "r"(a[1]), "r"(a[2]), "r"(a[3]), "r"(b0), "r"(b1));
}
#define SWZ(x) ((x) ^ (((x) >> 3) & 0x70))

// ---------------- param prep ----------------
__global__ void prep_lambda_kernel(const float* __restrict__ Lre,
                                   const float* __restrict__ Lim,
                                   const float* __restrict__ lstep)
{
    int p = blockIdx.x * blockDim.x + threadIdx.x;
    if (p >= PDIM) return;
    double lr = fmin((double)Lre[p], -1e-4);
    double li = (double)Lim[p];
    double s  = exp((double)lstep[p]);
    double er = exp(lr * s), th = li * s;
    double lbre = er * cos(th), lbim = er * sin(th);
    double den = lr * lr + li * li;
    double gre = lbre - 1.0, gim = lbim;
    g_lbc[p] = make_float2((float)lbre, (float)lbim);
    g_fac[p]        = (float)((gre * lr + gim * li) / den);
    g_fac[PDIM + p] = (float)((gim * lr - gre * li) / den);
    double er128 = exp(128.0 * lr * s), th128 = 128.0 * li * s;
    g_lb128c[p] = make_float2((float)(er128 * cos(th128)), (float)(er128 * sin(th128)));
}

__global__ void split_u_kernel(const float* __restrict__ u)
{
    size_t idx = (size_t)blockIdx.x * blockDim.x + threadIdx.x;
    size_t r = idx >> 8;
    int c = (int)(idx & 255) * 4;
    float4 v = *(const float4*)(u + r * 1024 + c);
    __half* o = g_uh + r * 1024;
    *(__half2*)(o + c)     = __floats2half2_rn(v.x, v.y);
    *(__half2*)(o + c + 2) = __floats2half2_rn(v.z, v.w);
}

// merged W1 + W2 prep
__global__ void split_w_kernel(const float* __restrict__ Bp,  // (P,H,2)
                               const float* __restrict__ Cp)  // (H,P,2)
{
    int bid = blockIdx.x;
    if (bid < 2048) {
        int idx = bid * blockDim.x + threadIdx.x;
        int p = idx >> 10, h = idx & 1023;
        float b0 = Bp[p * 2048 + h * 2 + 0];
        float b1 = Bp[p * 2048 + h * 2 + 1];
        float fr = g_fac[p], fi = g_fac[PDIM + p];
        g_w1h[(size_t)(2 * p)     * 1024 + h] = __float2half_rn((fr * b0 - fi * b1) * S1_SCALE);
        g_w1h[(size_t)(2 * p + 1) * 1024 + h] = __float2half_rn((fr * b1 + fi * b0) * S1_SCALE);
    } else {
        int idx = (bid - 2048) * blockDim.x + threadIdx.x;
        int h = idx >> 9, p = idx & 511;
        g_w2h[(size_t)h * 1024 + 2 * p]     = __float2half_rn( Cp[h * 1024 + p * 2 + 0]);
        g_w2h[(size_t)h * 1024 + 2 * p + 1] = __float2half_rn(-Cp[h * 1024 + p * 2 + 1]);
    }
}

// ---------------- HMMA fp16 GEMM: C = A(Mx1024) * B(1024x1024)^T ----
// 128 threads, 2x2 warp grid, 64x64 warp tile (MMA:LDSM ratio 4.0).
// MODE 0 (GEMM1): epilogue = in-CTA scan over the 128-row chunk.
// MODE 1 (GEMM2): epilogue = += D * u, fp32 out.
#define STAGE_BYTES 32768
#define SMEM_SZ (3 * STAGE_BYTES)
#define NCH 16

__device__ __forceinline__ void load_chunk_async(
    const __half* __restrict__ A, const __half* __restrict__ B,
    int bm, int bn, int c, uint32_t sA, uint32_t sB, int tid)
{
    int col = c * 64;
    const char* Ag = (const char*)(A + (size_t)bm * 1024 + col);
    const char* Bg = (const char*)(B + (size_t)bn * 1024 + col);
    #pragma unroll
    for (int i = 0; i < 8; i++) {
        int idx = tid + (i << 7);
        int row = idx >> 3, ch = (idx & 7) << 4;
        CP_ASYNC16(sA + SWZ(row * 128 + ch), Ag + (size_t)row * 2048 + ch);
    }
    #pragma unroll
    for (int i = 0; i < 8; i++) {
        int idx = tid + (i << 7);
        int row = idx >> 3, ch = (idx & 7) << 4;
        CP_ASYNC16(sB + SWZ(row * 128 + ch), Bg + (size_t)row * 2048 + ch);
    }
}

template<int MODE>
__global__ void __launch_bounds__(128, 2)
gemm_mma(const __half* __restrict__ A, const __half* __restrict__ Bm,
         float* __restrict__ Cout, const float* __restrict__ Dv,
         const __half* __restrict__ Uh)
{
    extern __shared__ char smem[];
    const uint32_t sbase = smem_u32(smem);
    const int tid = threadIdx.x;
    const int lane = tid & 31, wid = tid >> 5;
    const int wm = wid & 1, wn = wid >> 1;   // 2 x 2 warp grid: 64 rows x 64 cols each
    const int bm = blockIdx.y * 128, bn = blockIdx.x * 128;

    uint32_t sA[3], sB[3];
    #pragma unroll
    for (int s = 0; s < 3; s++) { sA[s] = sbase + s * STAGE_BYTES; sB[s] = sA[s] + 16384; }

    load_chunk_async(A, Bm, bm, bn, 0, sA[0], sB[0], tid); CP_COMMIT();
    load_chunk_async(A, Bm, bm, bn, 1, sA[1], sB[1], tid); CP_COMMIT();

    float acc[4][8][4];
    #pragma unroll
    for (int i = 0; i < 4; i++)
        #pragma unroll
        for (int j = 0; j < 8; j++)
            #pragma unroll
            for (int k = 0; k < 4; k++) acc[i][j][k] = 0.0f;

    const int arow = wm * 64 + (lane & 15);
    const int brow = wn * 64 + (lane & 15);
    const int khalf = (lane >> 4) * 16;

    #pragma unroll 1
    for (int c = 0; c < NCH; c++) {
        CP_WAIT1();
        __syncthreads();
        if (c + 2 < NCH)
            load_chunk_async(A, Bm, bm, bn, c + 2, sA[(c + 2) % 3], sB[(c + 2) % 3], tid);
        CP_COMMIT();

        const uint32_t a = sA[c % 3], b = sB[c % 3];
        #pragma unroll
        for (int ks = 0; ks < 4; ks++) {
            const int kb = ks * 32 + khalf;
            uint32_t af[4][4];
            #pragma unroll
            for (int mt = 0; mt < 4; mt++)
                ldsm4(af[mt], a + SWZ((arow + mt * 16) * 128 + kb));
            #pragma unroll
            for (int np = 0; np < 4; np++) {
                uint32_t bf[4];
                ldsm4(bf, b + SWZ((brow + np * 16) * 128 + kb));
                #pragma unroll
                for (int mt = 0; mt < 4; mt++) {
                    mma16816(acc[mt][np * 2 + 0], af[mt], bf[0], bf[2]);
                    mma16816(acc[mt][np * 2 + 1], af[mt], bf[1], bf[3]);
                }
            }
        }
    }

    if (MODE == 1) {
        // epilogue: += D*u, fp32 out
        #pragma unroll
        for (int mt = 0; mt < 4; mt++) {
            #pragma unroll
            for (int nt = 0; nt < 8; nt++) {
                const int row = bm + wm * 64 + mt * 16 + (lane >> 2);
                const int col = bn + wn * 64 + nt * 8 + (lane & 3) * 2;
                float d0 = acc[mt][nt][0], d1 = acc[mt][nt][1];
                float d2 = acc[mt][nt][2], d3 = acc[mt][nt][3];
                float2 dv = *(const float2*)(Dv + col);
                float2 u0 = __half22float2(*(const __half2*)(Uh + (size_t)row * 1024 + col));
                float2 u1 = __half22float2(*(const __half2*)(Uh + (size_t)(row + 8) * 1024 + col));
                d0 = fmaf(dv.x, u0.x, d0); d1 = fmaf(dv.y, u0.y, d1);
                d2 = fmaf(dv.x, u1.x, d2); d3 = fmaf(dv.y, u1.y, d3);
                *(float2*)(Cout + (size_t)row * 1024 + col)       = make_float2(d0, d1);
                *(float2*)(Cout + (size_t)(row + 8) * 1024 + col) = make_float2(d2, d3);
            }
        }
    } else {
        // epilogue: in-CTA scan over the chunk (128 l-steps x 64 complex states)
        __syncthreads();
        float* st = (float*)smem;  // [128][130]
        #pragma unroll
        for (int mt = 0; mt < 4; mt++) {
            #pragma unroll
            for (int nt = 0; nt < 8; nt++) {
                const int row = wm * 64 + mt * 16 + (lane >> 2);
                const int col = wn * 64 + nt * 8 + (lane & 3) * 2;
                *(float2*)&st[row * 130 + col]       = make_float2(acc[mt][nt][0], acc[mt][nt][1]);
                *(float2*)&st[(row + 8) * 130 + col] = make_float2(acc[mt][nt][2], acc[mt][nt][3]);
            }
        }
        __syncthreads();
        if (tid < 64) {
            const int p = (bn >> 1) + tid;
            const float2 lb = g_lbc[p];
            float xr = 0.0f, xi = 0.0f;
            __half* xout = g_xsh + (size_t)bm * 1024 + bn + 2 * tid;
            #pragma unroll 4
            for (int l = 0; l < 128; l++) {
                float2 v = *(float2*)&st[l * 130 + 2 * tid];
                float nr = fmaf(lb.x, xr, fmaf(-lb.y, xi, v.x));
                float ni = fmaf(lb.x, xi, fmaf( lb.y, xr, v.y));
                xr = nr; xi = ni;
                *(__half2*)(xout + (size_t)l * 1024) = __floats2half2_rn(xr, xi);
            }
            g_cs2[(bm >> 7) * PDIM + p] = make_float2(xr, xi);
        }
    }
}

// ---------------- cross-chunk carry scan (2 states / thread) ----------------
__global__ void scan_pass2()   // 2048 threads: (b, p-pair)
{
    int idx = blockIdx.x * blockDim.x + threadIdx.x;
    int b = idx >> 8, q = idx & 255;
    int p0 = 2 * q;
    float2 a0 = g_lb128c[p0], a1 = g_lb128c[p0 + 1];
    float4 c = make_float4(0.f, 0.f, 0.f, 0.f);
    for (int k = 0; k < NCHK; k++) {
        int j = (b * NCHK + k) * PDIM + p0;
        *(float4*)(g_ci2 + j) = c;
        float4 s = *(const float4*)(g_cs2 + j);
        float nr0 = fmaf(a0.x, c.x, fmaf(-a0.y, c.y, s.x));
        float ni0 = fmaf(a0.x, c.y, fmaf( a0.y, c.x, s.y));
        float nr1 = fmaf(a1.x, c.z, fmaf(-a1.y, c.w, s.z));
        float ni1 = fmaf(a1.x, c.w, fmaf( a1.y, c.z, s.w));
        c = make_float4(nr0, ni0, nr1, ni1);
    }
}

// pass3: in-place correction  x_l = xs_local_l + lb^{l+1} * carry, unscale.
__global__ void scan_pass3()   // 65536 threads: (chunk, p-pair)
{
    int idx = blockIdx.x * blockDim.x + threadIdx.x;
    int chunk = idx >> 8, q = idx & 255;
    int p0 = 2 * q;
    const float2 lb0 = g_lbc[p0], lb1 = g_lbc[p0 + 1];
    float4 c = *(const float4*)(g_ci2 + chunk * PDIM + p0);
    __half* xs = g_xsh + (size_t)chunk * 128 * 1024 + 4 * q;
    #pragma unroll 4
    for (int l = 0; l < 128; l++) {
        float nr0 = lb0.x * c.x - lb0.y * c.y;
        float ni0 = lb0.x * c.y + lb0.y * c.x;
        float nr1 = lb1.x * c.z - lb1.y * c.w;
        float ni1 = lb1.x * c.w + lb1.y * c.z;
        c = make_float4(nr0, ni0, nr1, ni1);
        uint2* ptr = (uint2*)(xs + (size_t)l * 1024);
        uint2 raw = *ptr;
        float2 v0 = __half22float2(*(__half2*)&raw.x);
        float2 v1 = __half22float2(*(__half2*)&raw.y);
        __half2 o0 = __floats2half2_rn((v0.x + c.x) * S1_INV, (v0.y + c.y) * S1_INV);
        __half2 o1 = __floats2half2_rn((v1.x + c.z) * S1_INV, (v1.y + c.w) * S1_INV);
        uint2 outw;
        outw.x = *(uint32_t*)&o0;
        outw.y = *(uint32_t*)&o1;
        *ptr = outw;
    }
}

// ---------------- launcher ----------------
extern "C" void kernel_launch(void* const* d_in, const int* in_sizes, int n_in,
                              void* d_out, int out_size)
{
    const float* u     = (const float*)d_in[0];
    const float* Lre   = (const float*)d_in[1];
    const float* Lim   = (const float*)d_in[2];
    const float* Bp    = (const float*)d_in[3];
    const float* Cp    = (const float*)d_in[4];
    const float* Dv    = (const float*)d_in[5];
    const float* lstep = (const float*)d_in[6];
    float* out = (float*)d_out;

    void *puh, *pw1, *pw2, *pxs;
    cudaGetSymbolAddress(&puh, g_uh);
    cudaGetSymbolAddress(&pw1, g_w1h);
    cudaGetSymbolAddress(&pw2, g_w2h);
    cudaGetSymbolAddress(&pxs, g_xsh);

    cudaFuncSetAttribute((const void*)gemm_mma<0>,
                         cudaFuncAttributeMaxDynamicSharedMemorySize, SMEM_SZ);
    cudaFuncSetAttribute((const void*)gemm_mma<1>,
                         cudaFuncAttributeMaxDynamicSharedMemorySize, SMEM_SZ);

    // launch order keeps gemm_mma<0> at index 3 (ncu capture slot)
    prep_lambda_kernel<<<2, 256>>>(Lre, Lim, lstep);          // 0
    split_u_kernel<<<MTOT, 256>>>(u);                          // 1
    split_w_kernel<<<4096, 256>>>(Bp, Cp);                     // 2

    dim3 grid(1024 / 128, MTOT / 128);   // (8, 256)
    gemm_mma<0><<<grid, 128, SMEM_SZ>>>((const __half*)puh, (const __half*)pw1,
                                        nullptr, nullptr, nullptr);   // 3 <- profiled
    scan_pass2<<<8, 256>>>();                                  // 4
    scan_pass3<<<256, 256>>>();                                // 5
    gemm_mma<1><<<grid, 128, SMEM_SZ>>>((const __half*)pxs, (const __half*)pw2,
                                        out, Dv, (const __half*)puh); // 6
}

// round 12
// speedup vs baseline: 1.1199x; 1.1199x over previous
#include <cuda_runtime.h>
#include <cuda_fp16.h>
#include <math.h>
#include <stdint.h>

// ---------------- problem dims (fixed) ----------------
#define BSZ   8
#define LSEQ  4096
#define HDIM  1024
#define PDIM  512
#define MTOT  (BSZ * LSEQ)        // 32768
#define CHUNKL 128
#define NCHK  (LSEQ / CHUNKL)     // 32
#define NCHUNKS_TOT (BSZ * NCHK)  // 256

#define S1_SCALE 1024.0f
#define S1_INV   (1.0f / 1024.0f)

// ---------------- device scratch ----------------
__device__ float2 g_lbc   [PDIM];               // lambda_bar
__device__ float2 g_lb32c [PDIM];               // lambda_bar^32
__device__ float2 g_lb128c[PDIM];               // lambda_bar^128
__device__ float  g_fac   [2 * PDIM];
__device__ __half g_uh  [(size_t)MTOT * 1024];
__device__ __half g_w1h [(size_t)1024 * 1024];  // rows interleaved: 2p=Re, 2p+1=Im (scaled)
__device__ __half g_w2h [(size_t)1024 * 1024];  // cols interleaved: 2p=C_re, 2p+1=-C_im
__device__ __half g_xsh [(size_t)MTOT * 1024];  // final xs fp16 (unscaled)
__device__ float2 g_cs2 [NCHUNKS_TOT * PDIM];   // per-chunk inclusive carries (scaled)
__device__ int    g_flag[NCHUNKS_TOT * 8];      // per (by,bx) ready flags

// ---------------- PTX helpers ----------------
__device__ __forceinline__ uint32_t smem_u32(const void* p) {
    uint32_t a;
    asm("{ .reg .u64 t; cvta.to.shared.u64 t, %1; cvt.u32.u64 %0, t; }" : "=r"(a) : "l"(p));
    return a;
}
#define CP_ASYNC16(dst, src) \
    asm volatile("cp.async.cg.shared.global [%0], [%1], 16;" :: "r"(dst), "l"(src) : "memory")
#define CP_COMMIT() asm volatile("cp.async.commit_group;" ::: "memory")
#define CP_WAIT1()  asm volatile("cp.async.wait_group 1;" ::: "memory")

__device__ __forceinline__ void ldsm4(uint32_t* r, uint32_t addr) {
    asm volatile("ldmatrix.sync.aligned.m8n8.x4.shared.b16 {%0,%1,%2,%3}, [%4];"
                 : "=r"(r[0]), "=r"(r[1]), "=r"(r[2]), "=r"(r[3]) : "r"(addr));
}
__device__ __forceinline__ void mma16816(float* d, const uint32_t* a, uint32_t b0, uint32_t b1) {
    asm volatile("mma.sync.aligned.m16n8k16.row.col.f32.f16.f16.f32 "
                 "{%0,%1,%2,%3}, {%4,%5,%6,%7}, {%8,%9}, {%0,%1,%2,%3};"
                 : "+f"(d[0]), "+f"(d[1]), "+f"(d[2]), "+f"(d[3])
                 : "r"(a[0]), "r"(a[1]), "r"(a[2]), "r"(a[3]), "r"(b0), "r"(b1));
}
#define SWZ(x) ((x) ^ (((x) >> 3) & 0x70))

// ---------------- param prep (also zeroes lookback flags) ----------------
__global__ void prep_lambda_kernel(const float* __restrict__ Lre,
                                   const float* __restrict__ Lim,
                                   const float* __restrict__ lstep)
{
    int t = blockIdx.x * blockDim.x + threadIdx.x;   // 0..511
    #pragma unroll
    for (int i = t; i < NCHUNKS_TOT * 8; i += 512) g_flag[i] = 0;

    int p = t;
    if (p >= PDIM) return;
    double lr = fmin((double)Lre[p], -1e-4);
    double li = (double)Lim[p];
    double s  = exp((double)lstep[p]);
    double er = exp(lr * s), th = li * s;
    double lbre = er * cos(th), lbim = er * sin(th);
    double den = lr * lr + li * li;
    double gre = lbre - 1.0, gim = lbim;
    g_lbc[p] = make_float2((float)lbre, (float)lbim);
    g_fac[p]        = (float)((gre * lr + gim * li) / den);
    g_fac[PDIM + p] = (float)((gim * lr - gre * li) / den);
    double er32 = exp(32.0 * lr * s), th32 = 32.0 * li * s;
    g_lb32c[p] = make_float2((float)(er32 * cos(th32)), (float)(er32 * sin(th32)));
    double er128 = exp(128.0 * lr * s), th128 = 128.0 * li * s;
    g_lb128c[p] = make_float2((float)(er128 * cos(th128)), (float)(er128 * sin(th128)));
}

__global__ void split_u_kernel(const float* __restrict__ u)
{
    size_t idx = (size_t)blockIdx.x * blockDim.x + threadIdx.x;
    size_t r = idx >> 8;
    int c = (int)(idx & 255) * 4;
    float4 v = *(const float4*)(u + r * 1024 + c);
    __half* o = g_uh + r * 1024;
    *(__half2*)(o + c)     = __floats2half2_rn(v.x, v.y);
    *(__half2*)(o + c + 2) = __floats2half2_rn(v.z, v.w);
}

// merged W1 + W2 prep
__global__ void split_w_kernel(const float* __restrict__ Bp,  // (P,H,2)
                               const float* __restrict__ Cp)  // (H,P,2)
{
    int bid = blockIdx.x;
    if (bid < 2048) {
        int idx = bid * blockDim.x + threadIdx.x;
        int p = idx >> 10, h = idx & 1023;
        float b0 = Bp[p * 2048 + h * 2 + 0];
        float b1 = Bp[p * 2048 + h * 2 + 1];
        float fr = g_fac[p], fi = g_fac[PDIM + p];
        g_w1h[(size_t)(2 * p)     * 1024 + h] = __float2half_rn((fr * b0 - fi * b1) * S1_SCALE);
        g_w1h[(size_t)(2 * p + 1) * 1024 + h] = __float2half_rn((fr * b1 + fi * b0) * S1_SCALE);
    } else {
        int idx = (bid - 2048) * blockDim.x + threadIdx.x;
        int h = idx >> 9, p = idx & 511;
        g_w2h[(size_t)h * 1024 + 2 * p]     = __float2half_rn( Cp[h * 1024 + p * 2 + 0]);
        g_w2h[(size_t)h * 1024 + 2 * p + 1] = __float2half_rn(-Cp[h * 1024 + p * 2 + 1]);
    }
}

// ---------------- HMMA fp16 GEMM: C = A(Mx1024) * B(1024x1024)^T ----
// 256 threads, 4x2 warp grid, 32x64 warp tile (proven optimum).
// MODE 0 (GEMM1): epilogue = full scan via decoupled lookback -> final xs.
// MODE 1 (GEMM2): epilogue = += D * u, fp32 out.
#define STAGE_BYTES 32768
#define SMEM_SZ (3 * STAGE_BYTES)
#define NCH 16

__device__ __forceinline__ void load_chunk_async(
    const __half* __restrict__ A, const __half* __restrict__ B,
    int bm, int bn, int c, uint32_t sA, uint32_t sB, int tid)
{
    int col = c * 64;
    const char* Ag = (const char*)(A + (size_t)bm * 1024 + col);
    const char* Bg = (const char*)(B + (size_t)bn * 1024 + col);
    #pragma unroll
    for (int i = 0; i < 4; i++) {
        int idx = tid + (i << 8);
        int row = idx >> 3, ch = (idx & 7) << 4;
        CP_ASYNC16(sA + SWZ(row * 128 + ch), Ag + (size_t)row * 2048 + ch);
    }
    #pragma unroll
    for (int i = 0; i < 4; i++) {
        int idx = tid + (i << 8);
        int row = idx >> 3, ch = (idx & 7) << 4;
        CP_ASYNC16(sB + SWZ(row * 128 + ch), Bg + (size_t)row * 2048 + ch);
    }
}

template<int MODE>
__global__ void __launch_bounds__(256, 2)
gemm_mma(const __half* __restrict__ A, const __half* __restrict__ Bm,
         float* __restrict__ Cout, const float* __restrict__ Dv,
         const __half* __restrict__ Uh)
{
    extern __shared__ char smem[];
    const uint32_t sbase = smem_u32(smem);
    const int tid = threadIdx.x;
    const int lane = tid & 31, wid = tid >> 5;
    const int wm = wid & 3, wn = wid >> 2;   // 4 x 2 warp grid: 32 rows x 64 cols
    const int by = blockIdx.y;
    // MODE 0: k-major chunk mapping (by = k*8 + b) so carry chains spread across waves
    const int bq = by & 7;          // batch b
    const int kq = by >> 3;         // chunk k within sequence
    const int bm = (MODE == 0) ? (bq * NCHK + kq) * 128 : by * 128;
    const int bn = blockIdx.x * 128;

    uint32_t sA[3], sB[3];
    #pragma unroll
    for (int s = 0; s < 3; s++) { sA[s] = sbase + s * STAGE_BYTES; sB[s] = sA[s] + 16384; }

    load_chunk_async(A, Bm, bm, bn, 0, sA[0], sB[0], tid); CP_COMMIT();
    load_chunk_async(A, Bm, bm, bn, 1, sA[1], sB[1], tid); CP_COMMIT();

    float acc[2][8][4];
    #pragma unroll
    for (int i = 0; i < 2; i++)
        #pragma unroll
        for (int j = 0; j < 8; j++)
            #pragma unroll
            for (int k = 0; k < 4; k++) acc[i][j][k] = 0.0f;

    const int arow = wm * 32 + (lane & 15);
    const int brow = wn * 64 + (lane & 15);
    const int khalf = (lane >> 4) * 16;

    #pragma unroll 1
    for (int c = 0; c < NCH; c++) {
        CP_WAIT1();
        __syncthreads();
        if (c + 2 < NCH)
            load_chunk_async(A, Bm, bm, bn, c + 2, sA[(c + 2) % 3], sB[(c + 2) % 3], tid);
        CP_COMMIT();

        const uint32_t a = sA[c % 3], b = sB[c % 3];
        #pragma unroll
        for (int ks = 0; ks < 4; ks++) {
            const int kb = ks * 32 + khalf;
            uint32_t af0[4], af1[4];
            ldsm4(af0, a + SWZ(arow * 128 + kb));
            ldsm4(af1, a + SWZ((arow + 16) * 128 + kb));
            #pragma unroll
            for (int np = 0; np < 4; np++) {
                uint32_t bf[4];
                ldsm4(bf, b + SWZ((brow + np * 16) * 128 + kb));
                mma16816(acc[0][np * 2 + 0], af0, bf[0], bf[2]);
                mma16816(acc[0][np * 2 + 1], af0, bf[1], bf[3]);
                mma16816(acc[1][np * 2 + 0], af1, bf[0], bf[2]);
                mma16816(acc[1][np * 2 + 1], af1, bf[1], bf[3]);
            }
        }
    }

    if (MODE == 1) {
        // epilogue: += D*u, fp32 out
        #pragma unroll
        for (int mt = 0; mt < 2; mt++) {
            #pragma unroll
            for (int nt = 0; nt < 8; nt++) {
                const int row = bm + wm * 32 + mt * 16 + (lane >> 2);
                const int col = bn + wn * 64 + nt * 8 + (lane & 3) * 2;
                float d0 = acc[mt][nt][0], d1 = acc[mt][nt][1];
                float d2 = acc[mt][nt][2], d3 = acc[mt][nt][3];
                float2 dv = *(const float2*)(Dv + col);
                float2 u0 = __half22float2(*(const __half2*)(Uh + (size_t)row * 1024 + col));
                float2 u1 = __half22float2(*(const __half2*)(Uh + (size_t)(row + 8) * 1024 + col));
                d0 = fmaf(dv.x, u0.x, d0); d1 = fmaf(dv.y, u0.y, d1);
                d2 = fmaf(dv.x, u1.x, d2); d3 = fmaf(dv.y, u1.y, d3);
                *(float2*)(Cout + (size_t)row * 1024 + col)       = make_float2(d0, d1);
                *(float2*)(Cout + (size_t)(row + 8) * 1024 + col) = make_float2(d2, d3);
            }
        }
    } else {
        // ---- fused full scan with decoupled lookback ----
        __syncthreads();
        float*  st   = (float*)smem;                       // [128][130] fp32
        float2* carr = (float2*)(smem + 128 * 130 * 4);    // [64] carry-ins
        #pragma unroll
        for (int mt = 0; mt < 2; mt++) {
            #pragma unroll
            for (int nt = 0; nt < 8; nt++) {
                const int row = wm * 32 + mt * 16 + (lane >> 2);
                const int col = wn * 64 + nt * 8 + (lane & 3) * 2;
                *(float2*)&st[row * 130 + col]       = make_float2(acc[mt][nt][0], acc[mt][nt][1]);
                *(float2*)&st[(row + 8) * 130 + col] = make_float2(acc[mt][nt][2], acc[mt][nt][3]);
            }
        }
        __syncthreads();
        if (tid < 64) {
            const int p = (bn >> 1) + tid;
            const float2 lb = g_lbc[p];
            // (A) local scan, in place (no dependence on carry)
            float xr = 0.0f, xi = 0.0f;
            #pragma unroll 4
            for (int l = 0; l < 128; l++) {
                float2 v = *(float2*)&st[l * 130 + 2 * tid];
                float nr = fmaf(lb.x, xr, fmaf(-lb.y, xi, v.x));
                float ni = fmaf(lb.x, xi, fmaf( lb.y, xr, v.y));
                xr = nr; xi = ni;
                *(float2*)&st[l * 130 + 2 * tid] = make_float2(xr, xi);
            }
            // (B) wait for predecessor carry
            float cr = 0.0f, ci = 0.0f;
            if (kq != 0) {
                volatile int* fl = (volatile int*)&g_flag[(by - 8) * 8 + blockIdx.x];
                while (*fl == 0) { }
                __threadfence();
                volatile float* cp = (volatile float*)&g_cs2[(size_t)(by - 8) * PDIM + p];
                cr = cp[0]; ci = cp[1];
            }
            // (C) publish inclusive carry-out IMMEDIATELY (short chain link)
            const float2 l128 = g_lb128c[p];
            float co_r = fmaf(l128.x, cr, fmaf(-l128.y, ci, xr));
            float co_i = fmaf(l128.x, ci, fmaf( l128.y, cr, xi));
            g_cs2[(size_t)by * PDIM + p] = make_float2(co_r, co_i);
            __threadfence();
            carr[tid] = make_float2(cr, ci);
        }
        __syncthreads();
        if (tid == 0) *(volatile int*)&g_flag[by * 8 + blockIdx.x] = 1;
        // (D) off-chain correction + final write by all 256 threads
        {
            const int s  = tid & 63;        // state within tile
            const int jq = tid >> 6;        // quarter of l-range
            const int p  = (bn >> 1) + s;
            const float2 lb = g_lbc[p];
            float2 cin = carr[s];
            // g = lb^(32*jq + 1) * cin
            float gr = cin.x, gi = cin.y;
            const float2 f32 = g_lb32c[p];
            #pragma unroll
            for (int t = 0; t < 3; t++) {
                if (t < jq) {
                    float tr = f32.x * gr - f32.y * gi;
                    float ti = f32.x * gi + f32.y * gr;
                    gr = tr; gi = ti;
                }
            }
            { float tr = lb.x * gr - lb.y * gi;
              float ti = lb.x * gi + lb.y * gr;
              gr = tr; gi = ti; }
            __half* xout = g_xsh + (size_t)(bm + jq * 32) * 1024 + bn + 2 * s;
            #pragma unroll 4
            for (int l = 0; l < 32; l++) {
                float2 v = *(float2*)&st[(jq * 32 + l) * 130 + 2 * s];
                *(__half2*)(xout + (size_t)l * 1024) =
                    __floats2half2_rn((v.x + gr) * S1_INV, (v.y + gi) * S1_INV);
                float tr = lb.x * gr - lb.y * gi;
                float ti = lb.x * gi + lb.y * gr;
                gr = tr; gi = ti;
            }
        }
    }
}

// ---------------- launcher ----------------
extern "C" void kernel_launch(void* const* d_in, const int* in_sizes, int n_in,
                              void* d_out, int out_size)
{
    const float* u     = (const float*)d_in[0];
    const float* Lre   = (const float*)d_in[1];
    const float* Lim   = (const float*)d_in[2];
    const float* Bp    = (const float*)d_in[3];
    const float* Cp    = (const float*)d_in[4];
    const float* Dv    = (const float*)d_in[5];
    const float* lstep = (const float*)d_in[6];
    float* out = (float*)d_out;

    void *puh, *pw1, *pw2, *pxs;
    cudaGetSymbolAddress(&puh, g_uh);
    cudaGetSymbolAddress(&pw1, g_w1h);
    cudaGetSymbolAddress(&pw2, g_w2h);
    cudaGetSymbolAddress(&pxs, g_xsh);

    cudaFuncSetAttribute((const void*)gemm_mma<0>,
                         cudaFuncAttributeMaxDynamicSharedMemorySize, SMEM_SZ);
    cudaFuncSetAttribute((const void*)gemm_mma<1>,
                         cudaFuncAttributeMaxDynamicSharedMemorySize, SMEM_SZ);

    // launch order keeps gemm_mma<0> at index 3 (ncu capture slot)
    prep_lambda_kernel<<<2, 256>>>(Lre, Lim, lstep);          // 0 (also zeroes flags)
    split_u_kernel<<<MTOT, 256>>>(u);                          // 1
    split_w_kernel<<<4096, 256>>>(Bp, Cp);                     // 2

    dim3 grid(1024 / 128, MTOT / 128);   // (8, 256)
    gemm_mma<0><<<grid, 256, SMEM_SZ>>>((const __half*)puh, (const __half*)pw1,
                                        nullptr, nullptr, nullptr);   // 3 <- profiled
    gemm_mma<1><<<grid, 256, SMEM_SZ>>>((const __half*)pxs, (const __half*)pw2,
                                        out, Dv, (const __half*)puh); // 4
}

// round 13
// speedup vs baseline: 1.1304x; 1.0094x over previous
#include <cuda_runtime.h>
#include <cuda_fp16.h>
#include <math.h>
#include <stdint.h>

// ---------------- problem dims (fixed) ----------------
#define BSZ   8
#define LSEQ  4096
#define HDIM  1024
#define PDIM  512
#define MTOT  (BSZ * LSEQ)        // 32768
#define CHUNKL 128
#define NCHK  (LSEQ / CHUNKL)     // 32
#define NCHUNKS_TOT (BSZ * NCHK)  // 256

#define S1_SCALE 1024.0f
#define S1_INV   (1.0f / 1024.0f)

// ---------------- device scratch ----------------
__device__ float2 g_lbc   [PDIM];               // lambda_bar
__device__ float2 g_lb32c [PDIM];               // lambda_bar^32
__device__ float2 g_lb128c[PDIM];               // lambda_bar^128
__device__ float  g_fac   [2 * PDIM];
__device__ __half g_uh  [(size_t)MTOT * 1024];
__device__ __half g_w1h [(size_t)1024 * 1024];  // rows interleaved: 2p=Re, 2p+1=Im (scaled)
__device__ __half g_w2h [(size_t)1024 * 1024];  // cols interleaved: 2p=C_re, 2p+1=-C_im
__device__ __half g_xsh [(size_t)MTOT * 1024];  // final xs fp16 (unscaled)
__device__ float2 g_cs2 [NCHUNKS_TOT * PDIM];   // per-chunk inclusive carries (scaled)
__device__ int    g_flag[NCHUNKS_TOT * 8];      // per (by,bx) ready flags

// ---------------- PTX helpers ----------------
__device__ __forceinline__ uint32_t smem_u32(const void* p) {
    uint32_t a;
    asm("{ .reg .u64 t; cvta.to.shared.u64 t, %1; cvt.u32.u64 %0, t; }" : "=r"(a) : "l"(p));
    return a;
}
#define CP_ASYNC16(dst, src) \
    asm volatile("cp.async.cg.shared.global [%0], [%1], 16;" :: "r"(dst), "l"(src) : "memory")
#define CP_COMMIT() asm volatile("cp.async.commit_group;" ::: "memory")
#define CP_WAIT1()  asm volatile("cp.async.wait_group 1;" ::: "memory")

__device__ __forceinline__ void ldsm4(uint32_t* r, uint32_t addr) {
    asm volatile("ldmatrix.sync.aligned.m8n8.x4.shared.b16 {%0,%1,%2,%3}, [%4];"
                 : "=r"(r[0]), "=r"(r[1]), "=r"(r[2]), "=r"(r[3]) : "r"(addr));
}
__device__ __forceinline__ void mma16816(float* d, const uint32_t* a, uint32_t b0, uint32_t b1) {
    asm volatile("mma.sync.aligned.m16n8k16.row.col.f32.f16.f16.f32 "
                 "{%0,%1,%2,%3}, {%4,%5,%6,%7}, {%8,%9}, {%0,%1,%2,%3};"
                 : "+f"(d[0]), "+f"(d[1]), "+f"(d[2]), "+f"(d[3])
                 : "r"(a[0]), "r"(a[1]), "r"(a[2]), "r"(a[3]), "r"(b0), "r"(b1));
}
#define SWZ(x) ((x) ^ (((x) >> 3) & 0x70))

// complex helpers
__device__ __forceinline__ float2 cmuladd(float2 a, float2 b, float2 c) {
    // a*b + c
    return make_float2(fmaf(a.x, b.x, fmaf(-a.y, b.y, c.x)),
                       fmaf(a.x, b.y, fmaf( a.y, b.x, c.y)));
}

// ---------------- param prep (also zeroes lookback flags) ----------------
__global__ void prep_lambda_kernel(const float* __restrict__ Lre,
                                   const float* __restrict__ Lim,
                                   const float* __restrict__ lstep)
{
    int t = blockIdx.x * blockDim.x + threadIdx.x;   // 0..511
    #pragma unroll
    for (int i = t; i < NCHUNKS_TOT * 8; i += 512) g_flag[i] = 0;

    int p = t;
    if (p >= PDIM) return;
    double lr = fmin((double)Lre[p], -1e-4);
    double li = (double)Lim[p];
    double s  = exp((double)lstep[p]);
    double er = exp(lr * s), th = li * s;
    double lbre = er * cos(th), lbim = er * sin(th);
    double den = lr * lr + li * li;
    double gre = lbre - 1.0, gim = lbim;
    g_lbc[p] = make_float2((float)lbre, (float)lbim);
    g_fac[p]        = (float)((gre * lr + gim * li) / den);
    g_fac[PDIM + p] = (float)((gim * lr - gre * li) / den);
    double er32 = exp(32.0 * lr * s), th32 = 32.0 * li * s;
    g_lb32c[p] = make_float2((float)(er32 * cos(th32)), (float)(er32 * sin(th32)));
    double er128 = exp(128.0 * lr * s), th128 = 128.0 * li * s;
    g_lb128c[p] = make_float2((float)(er128 * cos(th128)), (float)(er128 * sin(th128)));
}

__global__ void split_u_kernel(const float* __restrict__ u)
{
    size_t idx = (size_t)blockIdx.x * blockDim.x + threadIdx.x;
    size_t r = idx >> 8;
    int c = (int)(idx & 255) * 4;
    float4 v = *(const float4*)(u + r * 1024 + c);
    __half* o = g_uh + r * 1024;
    *(__half2*)(o + c)     = __floats2half2_rn(v.x, v.y);
    *(__half2*)(o + c + 2) = __floats2half2_rn(v.z, v.w);
}

// merged W1 + W2 prep
__global__ void split_w_kernel(const float* __restrict__ Bp,  // (P,H,2)
                               const float* __restrict__ Cp)  // (H,P,2)
{
    int bid = blockIdx.x;
    if (bid < 2048) {
        int idx = bid * blockDim.x + threadIdx.x;
        int p = idx >> 10, h = idx & 1023;
        float b0 = Bp[p * 2048 + h * 2 + 0];
        float b1 = Bp[p * 2048 + h * 2 + 1];
        float fr = g_fac[p], fi = g_fac[PDIM + p];
        g_w1h[(size_t)(2 * p)     * 1024 + h] = __float2half_rn((fr * b0 - fi * b1) * S1_SCALE);
        g_w1h[(size_t)(2 * p + 1) * 1024 + h] = __float2half_rn((fr * b1 + fi * b0) * S1_SCALE);
    } else {
        int idx = (bid - 2048) * blockDim.x + threadIdx.x;
        int h = idx >> 9, p = idx & 511;
        g_w2h[(size_t)h * 1024 + 2 * p]     = __float2half_rn( Cp[h * 1024 + p * 2 + 0]);
        g_w2h[(size_t)h * 1024 + 2 * p + 1] = __float2half_rn(-Cp[h * 1024 + p * 2 + 1]);
    }
}

// ---------------- HMMA fp16 GEMM: C = A(Mx1024) * B(1024x1024)^T ----
// 256 threads, 4x2 warp grid, 32x64 warp tile (proven optimum).
// MODE 0 (GEMM1): epilogue = fused scan, 4-quarter parallel + decoupled lookback.
// MODE 1 (GEMM2): epilogue = += D * u, fp32 out.
#define STAGE_BYTES 32768
#define SMEM_SZ (3 * STAGE_BYTES)
#define NCH 16

__device__ __forceinline__ void load_chunk_async(
    const __half* __restrict__ A, const __half* __restrict__ B,
    int bm, int bn, int c, uint32_t sA, uint32_t sB, int tid)
{
    int col = c * 64;
    const char* Ag = (const char*)(A + (size_t)bm * 1024 + col);
    const char* Bg = (const char*)(B + (size_t)bn * 1024 + col);
    #pragma unroll
    for (int i = 0; i < 4; i++) {
        int idx = tid + (i << 8);
        int row = idx >> 3, ch = (idx & 7) << 4;
        CP_ASYNC16(sA + SWZ(row * 128 + ch), Ag + (size_t)row * 2048 + ch);
    }
    #pragma unroll
    for (int i = 0; i < 4; i++) {
        int idx = tid + (i << 8);
        int row = idx >> 3, ch = (idx & 7) << 4;
        CP_ASYNC16(sB + SWZ(row * 128 + ch), Bg + (size_t)row * 2048 + ch);
    }
}

template<int MODE>
__global__ void __launch_bounds__(256, 2)
gemm_mma(const __half* __restrict__ A, const __half* __restrict__ Bm,
         float* __restrict__ Cout, const float* __restrict__ Dv,
         const __half* __restrict__ Uh)
{
    extern __shared__ char smem[];
    const uint32_t sbase = smem_u32(smem);
    const int tid = threadIdx.x;
    const int lane = tid & 31, wid = tid >> 5;
    const int wm = wid & 3, wn = wid >> 2;   // 4 x 2 warp grid
    const int by = blockIdx.y;
    const int bq = by & 7;          // batch b  (MODE 0 k-major map)
    const int kq = by >> 3;         // chunk k
    const int bm = (MODE == 0) ? (bq * NCHK + kq) * 128 : by * 128;
    const int bn = blockIdx.x * 128;

    uint32_t sA[3], sB[3];
    #pragma unroll
    for (int s = 0; s < 3; s++) { sA[s] = sbase + s * STAGE_BYTES; sB[s] = sA[s] + 16384; }

    load_chunk_async(A, Bm, bm, bn, 0, sA[0], sB[0], tid); CP_COMMIT();
    load_chunk_async(A, Bm, bm, bn, 1, sA[1], sB[1], tid); CP_COMMIT();

    float acc[2][8][4];
    #pragma unroll
    for (int i = 0; i < 2; i++)
        #pragma unroll
        for (int j = 0; j < 8; j++)
            #pragma unroll
            for (int k = 0; k < 4; k++) acc[i][j][k] = 0.0f;

    const int arow = wm * 32 + (lane & 15);
    const int brow = wn * 64 + (lane & 15);
    const int khalf = (lane >> 4) * 16;

    #pragma unroll 1
    for (int c = 0; c < NCH; c++) {
        CP_WAIT1();
        __syncthreads();
        if (c + 2 < NCH)
            load_chunk_async(A, Bm, bm, bn, c + 2, sA[(c + 2) % 3], sB[(c + 2) % 3], tid);
        CP_COMMIT();

        const uint32_t a = sA[c % 3], b = sB[c % 3];
        #pragma unroll
        for (int ks = 0; ks < 4; ks++) {
            const int kb = ks * 32 + khalf;
            uint32_t af0[4], af1[4];
            ldsm4(af0, a + SWZ(arow * 128 + kb));
            ldsm4(af1, a + SWZ((arow + 16) * 128 + kb));
            #pragma unroll
            for (int np = 0; np < 4; np++) {
                uint32_t bf[4];
                ldsm4(bf, b + SWZ((brow + np * 16) * 128 + kb));
                mma16816(acc[0][np * 2 + 0], af0, bf[0], bf[2]);
                mma16816(acc[0][np * 2 + 1], af0, bf[1], bf[3]);
                mma16816(acc[1][np * 2 + 0], af1, bf[0], bf[2]);
                mma16816(acc[1][np * 2 + 1], af1, bf[1], bf[3]);
            }
        }
    }

    if (MODE == 1) {
        // epilogue: += D*u, fp32 out
        #pragma unroll
        for (int mt = 0; mt < 2; mt++) {
            #pragma unroll
            for (int nt = 0; nt < 8; nt++) {
                const int row = bm + wm * 32 + mt * 16 + (lane >> 2);
                const int col = bn + wn * 64 + nt * 8 + (lane & 3) * 2;
                float d0 = acc[mt][nt][0], d1 = acc[mt][nt][1];
                float d2 = acc[mt][nt][2], d3 = acc[mt][nt][3];
                float2 dv = *(const float2*)(Dv + col);
                float2 u0 = __half22float2(*(const __half2*)(Uh + (size_t)row * 1024 + col));
                float2 u1 = __half22float2(*(const __half2*)(Uh + (size_t)(row + 8) * 1024 + col));
                d0 = fmaf(dv.x, u0.x, d0); d1 = fmaf(dv.y, u0.y, d1);
                d2 = fmaf(dv.x, u1.x, d2); d3 = fmaf(dv.y, u1.y, d3);
                *(float2*)(Cout + (size_t)row * 1024 + col)       = make_float2(d0, d1);
                *(float2*)(Cout + (size_t)(row + 8) * 1024 + col) = make_float2(d2, d3);
            }
        }
    } else {
        // ---- fused scan: 4-quarter parallel local scan + decoupled lookback ----
        __syncthreads();
        float*  st = (float*)smem;                              // [128][130]
        float2* qs = (float2*)(smem + 128 * 130 * 4);           // [4][64] quarter sums
        float2* qc = (float2*)(smem + 128 * 130 * 4 + 2048);    // [4][64] quarter carry-ins
        #pragma unroll
        for (int mt = 0; mt < 2; mt++) {
            #pragma unroll
            for (int nt = 0; nt < 8; nt++) {
                const int row = wm * 32 + mt * 16 + (lane >> 2);
                const int col = wn * 64 + nt * 8 + (lane & 3) * 2;
                *(float2*)&st[row * 130 + col]       = make_float2(acc[mt][nt][0], acc[mt][nt][1]);
                *(float2*)&st[(row + 8) * 130 + col] = make_float2(acc[mt][nt][2], acc[mt][nt][3]);
            }
        }
        __syncthreads();
        // Phase A: all 256 threads — zero-init local scan of a 32-step quarter
        {
            const int s  = tid & 63;
            const int jq = tid >> 6;
            const int p  = (bn >> 1) + s;
            const float2 lb = g_lbc[p];
            float2 x = make_float2(0.0f, 0.0f);
            float* base = &st[(jq * 32) * 130 + 2 * s];
            #pragma unroll 4
            for (int l = 0; l < 32; l++) {
                float2 v = *(float2*)(base + l * 130);
                x = cmuladd(lb, x, v);
                *(float2*)(base + l * 130) = x;
            }
            qs[jq * 64 + s] = x;
        }
        __syncthreads();
        // Phase B: 64 threads — combine quarters, lookback, publish, derive carry-ins
        if (tid < 64) {
            const int s = tid;
            const int p = (bn >> 1) + s;
            const float2 l32  = g_lb32c[p];
            const float2 l128 = g_lb128c[p];
            float2 q0 = qs[s], q1 = qs[64 + s], q2 = qs[128 + s], q3 = qs[192 + s];
            // pre-wait: chunk total T (zero-carry)
            float2 D1 = q0;
            float2 D2 = cmuladd(l32, D1, q1);
            float2 D3 = cmuladd(l32, D2, q2);
            float2 T  = cmuladd(l32, D3, q3);
            // wait for predecessor carry
            float2 cin = make_float2(0.0f, 0.0f);
            if (kq != 0) {
                volatile int* fl = (volatile int*)&g_flag[(by - 8) * 8 + blockIdx.x];
                while (*fl == 0) { }
                __threadfence();
                volatile float* cp = (volatile float*)&g_cs2[(size_t)(by - 8) * PDIM + p];
                cin.x = cp[0]; cin.y = cp[1];
            }
            // publish IMMEDIATELY: one cmul on the chain
            g_cs2[(size_t)by * PDIM + p] = cmuladd(l128, cin, T);
            __threadfence();
            // off-chain: quarter carry-ins C[j] = l32*C[j-1] + q[j-1]
            float2 C0 = cin;
            float2 C1 = cmuladd(l32, C0, q0);
            float2 C2 = cmuladd(l32, C1, q1);
            float2 C3 = cmuladd(l32, C2, q2);
            qc[s]       = C0;
            qc[64 + s]  = C1;
            qc[128 + s] = C2;
            qc[192 + s] = C3;
        }
        __syncthreads();
        if (tid == 0) *(volatile int*)&g_flag[by * 8 + blockIdx.x] = 1;
        // Phase C: 256 threads — apply correction x_l += lb^{l+1} * C_q, write fp16
        {
            const int s  = tid & 63;
            const int jq = tid >> 6;
            const int p  = (bn >> 1) + s;
            const float2 lb = g_lbc[p];
            float2 cq = qc[jq * 64 + s];
            float2 g = make_float2(lb.x * cq.x - lb.y * cq.y,
                                   lb.x * cq.y + lb.y * cq.x);
            const float* base = &st[(jq * 32) * 130 + 2 * s];
            __half* xout = g_xsh + (size_t)(bm + jq * 32) * 1024 + bn + 2 * s;
            #pragma unroll 4
            for (int l = 0; l < 32; l++) {
                float2 v = *(const float2*)(base + l * 130);
                *(__half2*)(xout + (size_t)l * 1024) =
                    __floats2half2_rn((v.x + g.x) * S1_INV, (v.y + g.y) * S1_INV);
                g = make_float2(lb.x * g.x - lb.y * g.y,
                                lb.x * g.y + lb.y * g.x);
            }
        }
    }
}

// ---------------- launcher ----------------
extern "C" void kernel_launch(void* const* d_in, const int* in_sizes, int n_in,
                              void* d_out, int out_size)
{
    const float* u     = (const float*)d_in[0];
    const float* Lre   = (const float*)d_in[1];
    const float* Lim   = (const float*)d_in[2];
    const float* Bp    = (const float*)d_in[3];
    const float* Cp    = (const float*)d_in[4];
    const float* Dv    = (const float*)d_in[5];
    const float* lstep = (const float*)d_in[6];
    float* out = (float*)d_out;

    void *puh, *pw1, *pw2, *pxs;
    cudaGetSymbolAddress(&puh, g_uh);
    cudaGetSymbolAddress(&pw1, g_w1h);
    cudaGetSymbolAddress(&pw2, g_w2h);
    cudaGetSymbolAddress(&pxs, g_xsh);

    cudaFuncSetAttribute((const void*)gemm_mma<0>,
                         cudaFuncAttributeMaxDynamicSharedMemorySize, SMEM_SZ);
    cudaFuncSetAttribute((const void*)gemm_mma<1>,
                         cudaFuncAttributeMaxDynamicSharedMemorySize, SMEM_SZ);

    // launch order keeps gemm_mma<0> at index 3 (ncu capture slot)
    prep_lambda_kernel<<<2, 256>>>(Lre, Lim, lstep);          // 0 (also zeroes flags)
    split_u_kernel<<<MTOT, 256>>>(u);                          // 1
    split_w_kernel<<<4096, 256>>>(Bp, Cp);                     // 2

    dim3 grid(1024 / 128, MTOT / 128);   // (8, 256)
    gemm_mma<0><<<grid, 256, SMEM_SZ>>>((const __half*)puh, (const __half*)pw1,
                                        nullptr, nullptr, nullptr);   // 3 <- profiled
    gemm_mma<1><<<grid, 256, SMEM_SZ>>>((const __half*)pxs, (const __half*)pw2,
                                        out, Dv, (const __half*)puh); // 4
}